// round 1
// baseline (speedup 1.0000x reference)
#include <cuda_runtime.h>
#include <math.h>

// Problem constants (fixed by the dataset)
#define BB    2
#define NN    2048
#define EE    32768
#define FIN   256
#define NH    8
#define HID   8
#define F1    64     // NH*HID
#define FOUT  64

// ---------------- scratch (device globals; no allocation allowed) -------------
__device__ float g_h1[BB * NN * F1];     // layer-1 post-W features (head-major blocks)
__device__ float g_s1[BB * NN * NH];     // per-head source scores
__device__ float g_s2[BB * NN * NH];     // per-head target scores
__device__ float g_x1[BB * NN * F1];     // elu(concat heads)
__device__ float g_h2[BB * NN * FOUT];   // layer-2 post-W features
__device__ float g_t1[BB * NN];          // layer-2 source score
__device__ float g_t2[BB * NN];          // layer-2 target score
__device__ int   g_cnt[NN];
__device__ int   g_offs[NN + 1];
__device__ int   g_tgt[EE];              // CSR target lists (dups marked -1)
__device__ float g_mean1[BB * F1];
__device__ float g_mean2[BB * FOUT];
__device__ float g_lse[BB * FOUT];

// ---------------- CSR build ---------------------------------------------------
__global__ void k_zero_cnt() {
    int i = blockIdx.x * blockDim.x + threadIdx.x;
    if (i < NN) g_cnt[i] = 0;
}

__global__ void k_count(const int* __restrict__ edges) {
    int i = blockIdx.x * blockDim.x + threadIdx.x;
    if (i < EE) atomicAdd(&g_cnt[edges[i]], 1);   // edges[0..E) = src
}

__global__ void k_scan() {
    __shared__ int ps[1024];
    int t = threadIdx.x;
    int a = g_cnt[2 * t], b = g_cnt[2 * t + 1];
    ps[t] = a + b;
    __syncthreads();
    for (int off = 1; off < 1024; off <<= 1) {
        int v   = ps[t];
        int add = (t >= off) ? ps[t - off] : 0;
        __syncthreads();
        ps[t] = v + add;
        __syncthreads();
    }
    int incl = ps[t];
    int excl = incl - (a + b);
    g_offs[2 * t]     = excl;
    g_offs[2 * t + 1] = excl + a;
    if (t == 1023) g_offs[2048] = incl;
}

__global__ void k_scatter(const int* __restrict__ edges) {
    int i = blockIdx.x * blockDim.x + threadIdx.x;
    if (i < EE) {
        int s   = edges[i];
        int pos = atomicAdd(&g_cnt[s], 1);
        g_tgt[g_offs[s] + pos] = edges[EE + i];   // tgt
    }
}

// Mark duplicate (src,tgt) pairs: reference's scatter-.set collapses them.
__global__ void k_dedup() {
    int n = blockIdx.x * blockDim.x + threadIdx.x;
    if (n >= NN) return;
    int st = g_offs[n], en = g_offs[n + 1];
    for (int i = st + 1; i < en; i++) {
        int t = g_tgt[i];
        if (t < 0) continue;
        for (int j = st; j < i; j++) {
            if (g_tgt[j] == t) { g_tgt[i] = -1; break; }
        }
    }
}

// ---------------- layer 1: h = x @ W_h (all heads) + per-head scores ----------
__global__ void k_gemm1(const float* __restrict__ x,
                        const float* __restrict__ Wh,
                        const float* __restrict__ ah) {
    int r = blockIdx.x;          // 0 .. B*N-1
    int j = threadIdx.x;         // 0 .. 63  (global feature = head*8 + o)
    __shared__ float sx[FIN];
    ((float4*)sx)[j] = ((const float4*)(x + (size_t)r * FIN))[j];
    __syncthreads();

    int h = j >> 3, o = j & 7;
    const float* w = Wh + h * FIN * HID + o;
    float acc = 0.f;
#pragma unroll 16
    for (int f = 0; f < FIN; f++) acc = fmaf(sx[f], w[f * HID], acc);
    g_h1[(size_t)r * F1 + j] = acc;

    float p1 = acc * ah[h * 16 + o];
    float p2 = acc * ah[h * 16 + 8 + o];
#pragma unroll
    for (int d = 1; d < 8; d <<= 1) {
        p1 += __shfl_xor_sync(0xffffffffu, p1, d);
        p2 += __shfl_xor_sync(0xffffffffu, p2, d);
    }
    if (o == 0) {
        g_s1[r * NH + h] = p1;
        g_s2[r * NH + h] = p2;
    }
}

// Column means (for zero-out-degree rows: softmax over all -1e20 is uniform 1/N)
__global__ void k_colmean(const float* __restrict__ src, float* __restrict__ dst) {
    int b = blockIdx.x;
    int t = threadIdx.x;         // 1024 threads: 16 row slices x 64 features
    int o = t & 63, sl = t >> 6;
    const float* base = src + ((size_t)b * NN + sl * 128) * 64 + o;
    float s = 0.f;
#pragma unroll 8
    for (int n = 0; n < 128; n++) s += base[n * 64];
    __shared__ float red[1024];
    red[t] = s;
    __syncthreads();
    for (int step = 512; step >= 64; step >>= 1) {
        if (t < step) red[t] += red[t + step];
        __syncthreads();
    }
    if (t < 64) dst[b * 64 + t] = red[t] * (1.0f / NN);
}

// Layer-1 attention: per-(b,src) row, sparse softmax over its edge list.
__global__ void k_att1(const float* __restrict__ bh) {
    int r = blockIdx.x;
    int b = r / NN, n = r % NN;
    int j = threadIdx.x;         // 64 threads
    int h = j >> 3;
    int st = g_offs[n], en = g_offs[n + 1];
    float bias = bh[h * HID + (j & 7)];
    float outv;
    if (st == en) {
        outv = g_mean1[b * F1 + j] + bias;
    } else {
        float s1v = g_s1[(b * NN + n) * NH + h];
        float m = -1e30f;
        for (int k = st; k < en; k++) {
            int t = g_tgt[k];
            if (t < 0) continue;
            float e = s1v + g_s2[(b * NN + t) * NH + h];
            e = (e >= 0.f) ? e : 0.2f * e;
            m = fmaxf(m, e);
        }
        float den = 0.f, acc = 0.f;
        for (int k = st; k < en; k++) {
            int t = g_tgt[k];
            if (t < 0) continue;
            float e = s1v + g_s2[(b * NN + t) * NH + h];
            e = (e >= 0.f) ? e : 0.2f * e;
            float w = expf(e - m);
            den += w;
            acc = fmaf(w, g_h1[((size_t)(b * NN + t)) * F1 + j], acc);
        }
        outv = acc / den + bias;
    }
    // ELU (alpha=1), matching jax.nn.elu's expm1 path
    g_x1[(size_t)(b * NN + n) * F1 + j] = (outv > 0.f) ? outv : expm1f(outv);
}

// ---------------- layer 2: h2 = x1 @ W_o + scores -----------------------------
__global__ void k_gemm2(const float* __restrict__ Wo,
                        const float* __restrict__ ao) {
    int r = blockIdx.x;
    int j = threadIdx.x;         // 64 threads
    __shared__ float sx[F1];
    sx[j] = g_x1[(size_t)r * F1 + j];
    __syncthreads();
    float acc = 0.f;
#pragma unroll 16
    for (int f = 0; f < F1; f++) acc = fmaf(sx[f], Wo[f * FOUT + j], acc);
    g_h2[(size_t)r * FOUT + j] = acc;

    float p1 = acc * ao[j];
    float p2 = acc * ao[64 + j];
#pragma unroll
    for (int d = 16; d >= 1; d >>= 1) {
        p1 += __shfl_xor_sync(0xffffffffu, p1, d);
        p2 += __shfl_xor_sync(0xffffffffu, p2, d);
    }
    __shared__ float rw[2][2];
    int warp = j >> 5, lane = j & 31;
    if (lane == 0) { rw[warp][0] = p1; rw[warp][1] = p2; }
    __syncthreads();
    if (j == 0) {
        g_t1[r] = rw[0][0] + rw[1][0];
        g_t2[r] = rw[0][1] + rw[1][1];
    }
}

__global__ void k_att2(const float* __restrict__ bo, float* __restrict__ out) {
    int r = blockIdx.x;
    int b = r / NN, n = r % NN;
    int j = threadIdx.x;         // 64 threads, single head
    int st = g_offs[n], en = g_offs[n + 1];
    float outv;
    if (st == en) {
        outv = g_mean2[b * FOUT + j] + bo[j];
    } else {
        float s1v = g_t1[b * NN + n];
        float m = -1e30f;
        for (int k = st; k < en; k++) {
            int t = g_tgt[k];
            if (t < 0) continue;
            float e = s1v + g_t2[b * NN + t];
            e = (e >= 0.f) ? e : 0.2f * e;
            m = fmaxf(m, e);
        }
        float den = 0.f, acc = 0.f;
        for (int k = st; k < en; k++) {
            int t = g_tgt[k];
            if (t < 0) continue;
            float e = s1v + g_t2[b * NN + t];
            e = (e >= 0.f) ? e : 0.2f * e;
            float w = expf(e - m);
            den += w;
            acc = fmaf(w, g_h2[((size_t)(b * NN + t)) * FOUT + j], acc);
        }
        outv = acc / den + bo[j];
    }
    out[(size_t)(b * NN + n) * FOUT + j] = outv;
}

// ---------------- log_softmax over the NODE axis (per (b, feature) column) ----
__global__ void k_lse(const float* __restrict__ out) {
    int b = blockIdx.x;
    int t = threadIdx.x;         // 1024: 16 slices x 64 features
    int o = t & 63, sl = t >> 6;
    const float* base = out + ((size_t)b * NN + sl * 128) * 64 + o;
    float m = -1e30f;
#pragma unroll 8
    for (int n = 0; n < 128; n++) m = fmaxf(m, base[n * 64]);
    __shared__ float red[1024];
    red[t] = m;
    __syncthreads();
    for (int step = 512; step >= 64; step >>= 1) {
        if (t < step) red[t] = fmaxf(red[t], red[t + step]);
        __syncthreads();
    }
    float mm = red[o];
    __syncthreads();
    float s = 0.f;
#pragma unroll 8
    for (int n = 0; n < 128; n++) s += expf(base[n * 64] - mm);
    red[t] = s;
    __syncthreads();
    for (int step = 512; step >= 64; step >>= 1) {
        if (t < step) red[t] += red[t + step];
        __syncthreads();
    }
    if (t < 64) g_lse[b * 64 + o] = mm + logf(red[o]);
}

__global__ void k_sub(float* __restrict__ out) {
    int i = blockIdx.x * blockDim.x + threadIdx.x;
    if (i < BB * NN * 64) {
        int b = i / (NN * 64);
        int o = i & 63;
        out[i] -= g_lse[b * 64 + o];
    }
}

// ---------------- launch -------------------------------------------------------
extern "C" void kernel_launch(void* const* d_in, const int* in_sizes, int n_in,
                              void* d_out, int out_size) {
    const float* x     = (const float*)d_in[0];
    const int*   edges = (const int*)  d_in[1];
    const float* Wh    = (const float*)d_in[2];
    const float* ah    = (const float*)d_in[3];
    const float* bh    = (const float*)d_in[4];
    const float* Wo    = (const float*)d_in[5];
    const float* ao    = (const float*)d_in[6];
    const float* bo    = (const float*)d_in[7];
    float* out = (float*)d_out;

    // CSR build (edges shared across batch)
    k_zero_cnt<<<NN / 256, 256>>>();
    k_count<<<EE / 256, 256>>>(edges);
    k_scan<<<1, 1024>>>();
    k_zero_cnt<<<NN / 256, 256>>>();
    k_scatter<<<EE / 256, 256>>>(edges);
    k_dedup<<<NN / 256, 256>>>();

    // layer 1
    k_gemm1<<<BB * NN, 64>>>(x, Wh, ah);
    {
        float* h1p; cudaGetSymbolAddress((void**)&h1p, g_h1);
        float* m1p; cudaGetSymbolAddress((void**)&m1p, g_mean1);
        k_colmean<<<BB, 1024>>>(h1p, m1p);
    }
    k_att1<<<BB * NN, 64>>>(bh);

    // layer 2
    k_gemm2<<<BB * NN, 64>>>(Wo, ao);
    {
        float* h2p; cudaGetSymbolAddress((void**)&h2p, g_h2);
        float* m2p; cudaGetSymbolAddress((void**)&m2p, g_mean2);
        k_colmean<<<BB, 1024>>>(h2p, m2p);
    }
    k_att2<<<BB * NN, 64>>>(bo, out);

    // log_softmax over node axis
    k_lse<<<BB, 1024>>>(out);
    k_sub<<<(BB * NN * 64 + 255) / 256, 256>>>(out);
}

// round 2
// speedup vs baseline: 1.2757x; 1.2757x over previous
#include <cuda_runtime.h>
#include <math.h>

// Problem constants (fixed by the dataset)
#define BB    2
#define NN    2048
#define EE    32768
#define FIN   256
#define NH    8
#define HID   8
#define F1    64     // NH*HID
#define FOUT  64

#define NB    256    // persistent blocks (co-resident: 148 SMs x 2)
#define NT    512    // threads per block
#define NWORDS (NN*NN/32)   // 131072 u32 dedup bitmap

// ---------------- scratch (device globals; no allocation allowed) -------------
__device__ float g_h1[BB * NN * F1];
__device__ float g_s1[BB * NN * NH];
__device__ float g_s2[BB * NN * NH];
__device__ float g_x1[BB * NN * F1];
__device__ float g_h2[BB * NN * FOUT];
__device__ float g_t1[BB * NN];
__device__ float g_t2[BB * NN];
__device__ int   g_cnt[NN];
__device__ int   g_offs[NN + 1];
__device__ int   g_tgt[EE];
__device__ unsigned g_bm[NWORDS];
__device__ float g_mean1[BB * F1];
__device__ float g_mean2[BB * FOUT];
__device__ unsigned long long g_bar[12];   // zero-init; monotonic across launches

// Grid barrier: generation-counting, no reset needed (each launch adds exactly
// NB per slot; target derived from arrival ticket). Launches are serialized by
// the harness, so brackets [NB*L, NB*L+NB) never interleave.
__device__ __forceinline__ void gridbar(int slot) {
    __threadfence();
    __syncthreads();
    if (threadIdx.x == 0) {
        unsigned long long old = atomicAdd(&g_bar[slot], 1ULL);
        unsigned long long target = (old / NB + 1ULL) * (unsigned long long)NB;
        volatile unsigned long long* p = (volatile unsigned long long*)&g_bar[slot];
        while (*p < target) __nanosleep(96);
    }
    __syncthreads();
}

__global__ void __launch_bounds__(NT, 2) mega(
    const float* __restrict__ x,
    const int*   __restrict__ edges,
    const float* __restrict__ Wh,
    const float* __restrict__ ah,
    const float* __restrict__ bh,
    const float* __restrict__ Wo,
    const float* __restrict__ ao,
    const float* __restrict__ bo,
    float* __restrict__ out)
{
    const int tid = threadIdx.x;
    const int bid = blockIdx.x;
    const int gi  = bid * NT + tid;          // 0 .. 131071

    __shared__ float sh[2048];               // x tile (8 rows x 256)
    __shared__ float sred[NT];
    __shared__ int   sint[NT];

    // ---------- P0: zero bitmap + counts ----------
    for (int i = gi; i < NWORDS + NN; i += NB * NT) {
        if (i < NWORDS) g_bm[i] = 0u;
        else            g_cnt[i - NWORDS] = 0;
    }
    gridbar(0);

    // ---------- P1: count out-degree ----------
    if (gi < EE) atomicAdd(&g_cnt[edges[gi]], 1);
    gridbar(1);

    // ---------- P2: scan (block 0) + rezero counts ----------
    if (bid == 0) {
        int c0 = __ldcg(&g_cnt[4 * tid + 0]);
        int c1 = __ldcg(&g_cnt[4 * tid + 1]);
        int c2 = __ldcg(&g_cnt[4 * tid + 2]);
        int c3 = __ldcg(&g_cnt[4 * tid + 3]);
        int s = c0 + c1 + c2 + c3;
        sint[tid] = s;
        __syncthreads();
        for (int off = 1; off < NT; off <<= 1) {
            int v = sint[tid];
            int a = (tid >= off) ? sint[tid - off] : 0;
            __syncthreads();
            sint[tid] = v + a;
            __syncthreads();
        }
        int excl = sint[tid] - s;
        g_offs[4 * tid + 0] = excl;
        g_offs[4 * tid + 1] = excl + c0;
        g_offs[4 * tid + 2] = excl + c0 + c1;
        g_offs[4 * tid + 3] = excl + c0 + c1 + c2;
        if (tid == NT - 1) g_offs[NN] = sint[tid];
        g_cnt[4 * tid + 0] = 0;
        g_cnt[4 * tid + 1] = 0;
        g_cnt[4 * tid + 2] = 0;
        g_cnt[4 * tid + 3] = 0;
    }
    gridbar(2);

    // ---------- P3: scatter with bitmap dedup ----------
    if (gi < EE) {
        int s = edges[gi];
        int t = edges[EE + gi];
        unsigned bitpos = (unsigned)s * NN + (unsigned)t;
        unsigned mask = 1u << (bitpos & 31u);
        unsigned old = atomicOr(&g_bm[bitpos >> 5], mask);
        if (!(old & mask)) {
            int pos = atomicAdd(&g_cnt[s], 1);
            g_tgt[g_offs[s] + pos] = t;
        }
    }
    gridbar(3);

    // ---------- P4: gemm1 (h1 = x @ Wh, all heads) + scores ----------
    {
        const int sub = tid >> 6, j = tid & 63;
        const int h = j >> 3, o = j & 7;
        for (int g = bid; g < (BB * NN) / 8; g += NB) {   // 512 groups, 2 iters
            int rbase = g * 8;
            {   // load 8x256 x-tile as float4
                int row = tid >> 6, c4 = tid & 63;
                ((float4*)sh)[tid] =
                    ((const float4*)(x + (size_t)(rbase + row) * FIN))[c4];
            }
            __syncthreads();
            const float* w  = Wh + h * (FIN * HID) + o;
            const float* xs = sh + sub * FIN;
            float a0 = 0.f, a1 = 0.f, a2 = 0.f, a3 = 0.f;
#pragma unroll 16
            for (int f = 0; f < FIN; f += 4) {
                a0 = fmaf(xs[f + 0], __ldg(&w[(f + 0) * HID]), a0);
                a1 = fmaf(xs[f + 1], __ldg(&w[(f + 1) * HID]), a1);
                a2 = fmaf(xs[f + 2], __ldg(&w[(f + 2) * HID]), a2);
                a3 = fmaf(xs[f + 3], __ldg(&w[(f + 3) * HID]), a3);
            }
            float acc = (a0 + a1) + (a2 + a3);
            int r = rbase + sub;
            g_h1[(size_t)r * F1 + j] = acc;
            float p1 = acc * __ldg(&ah[h * 16 + o]);
            float p2 = acc * __ldg(&ah[h * 16 + 8 + o]);
#pragma unroll
            for (int d = 1; d < 8; d <<= 1) {
                p1 += __shfl_xor_sync(0xffffffffu, p1, d);
                p2 += __shfl_xor_sync(0xffffffffu, p2, d);
            }
            if (o == 0) {
                g_s1[r * NH + h] = p1;
                g_s2[r * NH + h] = p2;
            }
            __syncthreads();
        }
    }
    gridbar(4);

    // ---------- P5: column mean of h1 (zero-degree fallback) ----------
    if (bid < BB * F1) {
        int b = bid >> 6, o = bid & 63;
        float s = 0.f;
#pragma unroll
        for (int q = 0; q < 4; q++) {
            int n = tid + NT * q;
            s += __ldcg(&g_h1[(size_t)(b * NN + n) * F1 + o]);
        }
        sred[tid] = s;
        __syncthreads();
        for (int step = NT / 2; step > 0; step >>= 1) {
            if (tid < step) sred[tid] += sred[tid + step];
            __syncthreads();
        }
        if (tid == 0) g_mean1[bid] = sred[0] * (1.0f / NN);
    }
    gridbar(5);

    // ---------- P6: att1 + ELU ----------
    {
        const int sub = tid >> 6, j = tid & 63;
        const int h = j >> 3, o = j & 7;
        const float bias = __ldg(&bh[h * HID + o]);
        for (int g = bid; g < (BB * NN) / 8; g += NB) {
            int r = g * 8 + sub;
            int b = r >> 11, n = r & (NN - 1);
            int st  = g_offs[n];
            int deg = __ldcg(&g_cnt[n]);
            float outv;
            if (deg == 0) {
                outv = __ldcg(&g_mean1[b * F1 + j]) + bias;
            } else {
                float s1v = __ldcg(&g_s1[(b * NN + n) * NH + h]);
                float m = -1e30f;
                for (int k = 0; k < deg; k++) {
                    int t = __ldcg(&g_tgt[st + k]);
                    float e = s1v + __ldcg(&g_s2[(b * NN + t) * NH + h]);
                    e = fmaxf(e, 0.2f * e);
                    m = fmaxf(m, e);
                }
                float den = 0.f, acc = 0.f;
                for (int k = 0; k < deg; k++) {
                    int t = __ldcg(&g_tgt[st + k]);
                    float e = s1v + __ldcg(&g_s2[(b * NN + t) * NH + h]);
                    e = fmaxf(e, 0.2f * e);
                    float wgt = __expf(e - m);
                    den += wgt;
                    acc = fmaf(wgt, __ldcg(&g_h1[(size_t)(b * NN + t) * F1 + j]), acc);
                }
                outv = acc / den + bias;
            }
            g_x1[(size_t)r * F1 + j] = (outv > 0.f) ? outv : (__expf(outv) - 1.0f);
        }
    }
    gridbar(6);

    // ---------- P7: gemm2 (h2 = x1 @ Wo) + scores ----------
    {
        const int sub = tid >> 6, j = tid & 63;
        for (int g = bid; g < (BB * NN) / 8; g += NB) {
            int rbase = g * 8;
            sh[tid] = g_x1[(size_t)rbase * F1 + tid];  // own P6 writes: same g->bid map
            __syncthreads();
            const float* xs = sh + sub * F1;
            float a0 = 0.f, a1 = 0.f, a2 = 0.f, a3 = 0.f;
#pragma unroll 16
            for (int f = 0; f < F1; f += 4) {
                a0 = fmaf(xs[f + 0], __ldg(&Wo[(f + 0) * FOUT + j]), a0);
                a1 = fmaf(xs[f + 1], __ldg(&Wo[(f + 1) * FOUT + j]), a1);
                a2 = fmaf(xs[f + 2], __ldg(&Wo[(f + 2) * FOUT + j]), a2);
                a3 = fmaf(xs[f + 3], __ldg(&Wo[(f + 3) * FOUT + j]), a3);
            }
            float acc = (a0 + a1) + (a2 + a3);
            int r = rbase + sub;
            g_h2[(size_t)r * FOUT + j] = acc;
            float p1 = acc * __ldg(&ao[j]);
            float p2 = acc * __ldg(&ao[FOUT + j]);
#pragma unroll
            for (int d = 16; d >= 1; d >>= 1) {
                p1 += __shfl_xor_sync(0xffffffffu, p1, d);
                p2 += __shfl_xor_sync(0xffffffffu, p2, d);
            }
            int warp = tid >> 5;
            if ((tid & 31) == 0) { sred[warp] = p1; sred[16 + warp] = p2; }
            __syncthreads();
            if (j == 0) {
                g_t1[r] = sred[2 * sub] + sred[2 * sub + 1];
                g_t2[r] = sred[16 + 2 * sub] + sred[16 + 2 * sub + 1];
            }
            __syncthreads();
        }
    }
    gridbar(7);

    // ---------- P8: column mean of h2 ----------
    if (bid < BB * FOUT) {
        int b = bid >> 6, o = bid & 63;
        float s = 0.f;
#pragma unroll
        for (int q = 0; q < 4; q++) {
            int n = tid + NT * q;
            s += __ldcg(&g_h2[(size_t)(b * NN + n) * FOUT + o]);
        }
        sred[tid] = s;
        __syncthreads();
        for (int step = NT / 2; step > 0; step >>= 1) {
            if (tid < step) sred[tid] += sred[tid + step];
            __syncthreads();
        }
        if (tid == 0) g_mean2[bid] = sred[0] * (1.0f / NN);
    }
    gridbar(8);

    // ---------- P9: att2 -> out ----------
    {
        const int sub = tid >> 6, j = tid & 63;
        const float bias = __ldg(&bo[j]);
        for (int g = bid; g < (BB * NN) / 8; g += NB) {
            int r = g * 8 + sub;
            int b = r >> 11, n = r & (NN - 1);
            int st  = g_offs[n];
            int deg = __ldcg(&g_cnt[n]);
            float outv;
            if (deg == 0) {
                outv = __ldcg(&g_mean2[b * FOUT + j]) + bias;
            } else {
                float s1v = __ldcg(&g_t1[b * NN + n]);
                float m = -1e30f;
                for (int k = 0; k < deg; k++) {
                    int t = __ldcg(&g_tgt[st + k]);
                    float e = s1v + __ldcg(&g_t2[b * NN + t]);
                    e = fmaxf(e, 0.2f * e);
                    m = fmaxf(m, e);
                }
                float den = 0.f, acc = 0.f;
                for (int k = 0; k < deg; k++) {
                    int t = __ldcg(&g_tgt[st + k]);
                    float e = s1v + __ldcg(&g_t2[b * NN + t]);
                    e = fmaxf(e, 0.2f * e);
                    float wgt = __expf(e - m);
                    den += wgt;
                    acc = fmaf(wgt, __ldcg(&g_h2[(size_t)(b * NN + t) * FOUT + j]), acc);
                }
                outv = acc / den + bias;
            }
            out[(size_t)r * FOUT + j] = outv;
        }
    }
    gridbar(9);

    // ---------- P10: log_softmax over node axis (per (b,feature) column) ----------
    if (bid < BB * FOUT) {
        int b = bid >> 6, o = bid & 63;
        float v[4];
#pragma unroll
        for (int q = 0; q < 4; q++) {
            int n = tid + NT * q;
            v[q] = __ldcg(&out[(size_t)(b * NN + n) * FOUT + o]);
        }
        float m = fmaxf(fmaxf(v[0], v[1]), fmaxf(v[2], v[3]));
        sred[tid] = m;
        __syncthreads();
        for (int step = NT / 2; step > 0; step >>= 1) {
            if (tid < step) sred[tid] = fmaxf(sred[tid], sred[tid + step]);
            __syncthreads();
        }
        float mm = sred[0];
        __syncthreads();
        float s = __expf(v[0] - mm) + __expf(v[1] - mm) +
                  __expf(v[2] - mm) + __expf(v[3] - mm);
        sred[tid] = s;
        __syncthreads();
        for (int step = NT / 2; step > 0; step >>= 1) {
            if (tid < step) sred[tid] += sred[tid + step];
            __syncthreads();
        }
        float lse = mm + __logf(sred[0]);
#pragma unroll
        for (int q = 0; q < 4; q++) {
            int n = tid + NT * q;
            out[(size_t)(b * NN + n) * FOUT + o] = v[q] - lse;
        }
    }
}

// ---------------- launch -------------------------------------------------------
extern "C" void kernel_launch(void* const* d_in, const int* in_sizes, int n_in,
                              void* d_out, int out_size) {
    const float* x     = (const float*)d_in[0];
    const int*   edges = (const int*)  d_in[1];
    const float* Wh    = (const float*)d_in[2];
    const float* ah    = (const float*)d_in[3];
    const float* bh    = (const float*)d_in[4];
    const float* Wo    = (const float*)d_in[5];
    const float* ao    = (const float*)d_in[6];
    const float* bo    = (const float*)d_in[7];
    float* out = (float*)d_out;

    mega<<<NB, NT>>>(x, edges, Wh, ah, bh, Wo, ao, bo, out);
}

// round 3
// speedup vs baseline: 1.8030x; 1.4134x over previous
#include <cuda_runtime.h>
#include <math.h>

// Problem constants (fixed by the dataset)
#define BB    2
#define NN    2048
#define EE    32768
#define FIN   256
#define NH    8
#define HID   8
#define F1    64
#define FOUT  64

#define NB    148     // exactly one block per SM
#define NT    1024
#define NWORDS (NN*NN/32)

// ---------------- scratch (device globals; zero-init at module load) ----------
__device__ float g_h1[BB * NN * F1];
__device__ float g_s1[BB * NN * NH];
__device__ float g_s2[BB * NN * NH];
__device__ float g_x1[BB * NN * F1];
__device__ float g_h2[BB * NN * FOUT];
__device__ float g_t1[BB * NN];
__device__ float g_t2[BB * NN];
__device__ int   g_cnt[NN];
__device__ int   g_offs[NN + 1];
__device__ int   g_tgt[EE];
__device__ unsigned g_bm[NWORDS];       // invariant: all-zero at launch entry
__device__ float g_mean1[BB * F1];      // invariant: zero at launch entry
__device__ float g_mean2[BB * FOUT];    // invariant: zero at launch entry
__device__ unsigned long long g_bar[8]; // monotonic generation counters

// Grid barrier: generation counting — no reset, safe across graph replays.
__device__ __forceinline__ void gridbar(int slot) {
    __threadfence();
    __syncthreads();
    if (threadIdx.x == 0) {
        unsigned long long old = atomicAdd(&g_bar[slot], 1ULL);
        unsigned long long target = (old / NB + 1ULL) * (unsigned long long)NB;
        volatile unsigned long long* p = (volatile unsigned long long*)&g_bar[slot];
        while (*p < target) { }
    }
    __syncthreads();
}

__global__ void __launch_bounds__(NT, 1) mega(
    const float* __restrict__ x,
    const int*   __restrict__ edges,
    const float* __restrict__ Wh,
    const float* __restrict__ ah,
    const float* __restrict__ bh,
    const float* __restrict__ Wo,
    const float* __restrict__ ao,
    const float* __restrict__ bo,
    float* __restrict__ out)
{
    const int tid = threadIdx.x;
    const int bid = blockIdx.x;

    __shared__ float sx[8192];      // 32KB: x tile / CSR counters
    __shared__ float sred[1024];    // 4KB : reductions / scan temp

    // ================= Phase 1: CSR build (block NB-1) || GEMM1 (blocks 0..127)
    if (bid == NB - 1) {
        int* scnt = (int*)sx;           // 2048 counters
        int* pps  = (int*)sred;         // 1024 scan temp
        for (int i = tid; i < NN; i += NT) scnt[i] = 0;
        __syncthreads();
        for (int i = tid; i < EE; i += NT) atomicAdd(&scnt[edges[i]], 1);
        __syncthreads();
        int a = scnt[2 * tid], b2 = scnt[2 * tid + 1];
        pps[tid] = a + b2;
        __syncthreads();
        for (int off = 1; off < NT; off <<= 1) {
            int v = pps[tid];
            int ad = (tid >= off) ? pps[tid - off] : 0;
            __syncthreads();
            pps[tid] = v + ad;
            __syncthreads();
        }
        int excl = pps[tid] - (a + b2);
        g_offs[2 * tid]     = excl;
        g_offs[2 * tid + 1] = excl + a;
        if (tid == NT - 1) g_offs[NN] = pps[tid];
        scnt[2 * tid]     = excl;          // write cursors
        scnt[2 * tid + 1] = excl + a;
        __syncthreads();
        for (int i = tid; i < EE; i += NT) {
            int s = edges[i], t = edges[EE + i];
            unsigned bit = (unsigned)s * NN + (unsigned)t;
            unsigned msk = 1u << (bit & 31u);
            unsigned old = atomicOr(&g_bm[bit >> 5], msk);
            if (!(old & msk)) {
                int slot = atomicAdd(&scnt[s], 1);
                g_tgt[slot] = t;
            }
        }
        __syncthreads();
        for (int n = tid; n < NN; n += NT) g_cnt[n] = scnt[n] - g_offs[n];
    } else if (bid < 128) {
        // GEMM1: 32-row tile, 2 rows/thread, h1 = x @ Wh + scores + mean atomics
        const int R = bid * 32;
        const int b = R >> 11;
        const float4* x4 = (const float4*)x + (size_t)R * (FIN / 4);
        float4* sx4 = (float4*)sx;
        for (int i = tid; i < 32 * (FIN / 4); i += NT) sx4[i] = x4[i];
        __syncthreads();
        const int j = tid & 63, rq = tid >> 6;        // 16 quads x 2 rows
        const int h = j >> 3, o = j & 7;
        const float* w   = Wh + h * (FIN * HID) + o;
        const float* xr0 = sx + (rq * 2) * FIN;
        const float* xr1 = xr0 + FIN;
        float a0 = 0.f, a1 = 0.f, c0 = 0.f, c1 = 0.f;
#pragma unroll 8
        for (int f = 0; f < FIN; f += 2) {
            float w0 = __ldg(&w[f * HID]);
            float w1 = __ldg(&w[(f + 1) * HID]);
            a0 = fmaf(xr0[f], w0, a0);     c0 = fmaf(xr1[f], w0, c0);
            a1 = fmaf(xr0[f + 1], w1, a1); c1 = fmaf(xr1[f + 1], w1, c1);
        }
        float acc0 = a0 + a1, acc1 = c0 + c1;
        int r0 = R + rq * 2, r1 = r0 + 1;
        g_h1[(size_t)r0 * F1 + j] = acc0;
        g_h1[(size_t)r1 * F1 + j] = acc1;
        float s1c = __ldg(&ah[h * 16 + o]);
        float s2c = __ldg(&ah[h * 16 + 8 + o]);
        float p10 = acc0 * s1c, p20 = acc0 * s2c;
        float p11 = acc1 * s1c, p21 = acc1 * s2c;
#pragma unroll
        for (int d = 1; d < 8; d <<= 1) {
            p10 += __shfl_xor_sync(0xffffffffu, p10, d);
            p20 += __shfl_xor_sync(0xffffffffu, p20, d);
            p11 += __shfl_xor_sync(0xffffffffu, p11, d);
            p21 += __shfl_xor_sync(0xffffffffu, p21, d);
        }
        if (o == 0) {
            g_s1[r0 * NH + h] = p10; g_s2[r0 * NH + h] = p20;
            g_s1[r1 * NH + h] = p11; g_s2[r1 * NH + h] = p21;
        }
        sred[tid] = acc0 + acc1;
        __syncthreads();
        for (int st = 512; st >= 64; st >>= 1) {
            if (tid < st) sred[tid] += sred[tid + st];
            __syncthreads();
        }
        if (tid < 64) atomicAdd(&g_mean1[b * F1 + tid], sred[tid] * (1.0f / NN));
    }
    gridbar(0);

    // ================= Phase 2: att1 + ELU (online softmax, L1-cached loads)
    {
        const int j = tid & 63, sub = tid >> 6;   // 16 rows per group
        const int h = j >> 3;
        const float bias = __ldg(&bh[j]);
        for (int g = bid; g < (BB * NN) / 16; g += NB) {
            int r = g * 16 + sub;
            int b = r >> 11, n = r & (NN - 1);
            int st = g_offs[n], deg = g_cnt[n];
            float outv;
            if (deg == 0) {
                outv = g_mean1[b * F1 + j] + bias;
            } else {
                float s1v = g_s1[(b * NN + n) * NH + h];
                float m = -1e30f, den = 0.f, acc = 0.f;
                for (int k = 0; k < deg; k++) {
                    int t = g_tgt[st + k];
                    float e = s1v + g_s2[(b * NN + t) * NH + h];
                    e = fmaxf(e, 0.2f * e);
                    float mn = fmaxf(m, e);
                    float sc = __expf(m - mn);
                    float wt = __expf(e - mn);
                    den = fmaf(den, sc, wt);
                    acc = fmaf(acc, sc, wt * g_h1[(size_t)(b * NN + t) * F1 + j]);
                    m = mn;
                }
                outv = acc / den + bias;
            }
            g_x1[(size_t)r * F1 + j] = (outv > 0.f) ? outv : (__expf(outv) - 1.0f);
        }
    }
    gridbar(1);

    // ================= Phase 3: GEMM2 + scores + mean2 (blocks 0..127)
    if (bid < 128) {
        const int R = bid * 32;
        const int b = R >> 11;
        for (int i = tid; i < 32 * F1; i += NT) sx[i] = g_x1[(size_t)R * F1 + i];
        __syncthreads();
        const int j = tid & 63, rq = tid >> 6;
        const float* xr0 = sx + (rq * 2) * F1;
        const float* xr1 = xr0 + F1;
        float a0 = 0.f, c0 = 0.f;
#pragma unroll 16
        for (int f = 0; f < F1; f++) {
            float wv = __ldg(&Wo[f * FOUT + j]);
            a0 = fmaf(xr0[f], wv, a0);
            c0 = fmaf(xr1[f], wv, c0);
        }
        int r0 = R + rq * 2, r1 = r0 + 1;
        g_h2[(size_t)r0 * FOUT + j] = a0;
        g_h2[(size_t)r1 * FOUT + j] = c0;
        float w1c = __ldg(&ao[j]), w2c = __ldg(&ao[FOUT + j]);
        float p10 = a0 * w1c, p20 = a0 * w2c;
        float p11 = c0 * w1c, p21 = c0 * w2c;
#pragma unroll
        for (int d = 16; d >= 1; d >>= 1) {
            p10 += __shfl_xor_sync(0xffffffffu, p10, d);
            p20 += __shfl_xor_sync(0xffffffffu, p20, d);
            p11 += __shfl_xor_sync(0xffffffffu, p11, d);
            p21 += __shfl_xor_sync(0xffffffffu, p21, d);
        }
        int warp = tid >> 5;
        if ((tid & 31) == 0) {
            sred[warp * 4 + 0] = p10; sred[warp * 4 + 1] = p20;
            sred[warp * 4 + 2] = p11; sred[warp * 4 + 3] = p21;
        }
        __syncthreads();
        if (tid < 64) {
            int rq2 = tid >> 2, which = tid & 3;
            float v = sred[(2 * rq2) * 4 + which] + sred[(2 * rq2 + 1) * 4 + which];
            int rr = R + rq2 * 2;
            if      (which == 0) g_t1[rr] = v;
            else if (which == 1) g_t2[rr] = v;
            else if (which == 2) g_t1[rr + 1] = v;
            else                 g_t2[rr + 1] = v;
        }
        __syncthreads();
        sred[tid] = a0 + c0;
        __syncthreads();
        for (int st = 512; st >= 64; st >>= 1) {
            if (tid < st) sred[tid] += sred[tid + st];
            __syncthreads();
        }
        if (tid < 64) atomicAdd(&g_mean2[b * FOUT + tid], sred[tid] * (1.0f / NN));
    }
    gridbar(2);

    // ================= Phase 4: att2 -> out
    {
        const int j = tid & 63, sub = tid >> 6;
        const float bias = __ldg(&bo[j]);
        for (int g = bid; g < (BB * NN) / 16; g += NB) {
            int r = g * 16 + sub;
            int b = r >> 11, n = r & (NN - 1);
            int st = g_offs[n], deg = g_cnt[n];
            float outv;
            if (deg == 0) {
                outv = g_mean2[b * FOUT + j] + bias;
            } else {
                float s1v = g_t1[b * NN + n];
                float m = -1e30f, den = 0.f, acc = 0.f;
                for (int k = 0; k < deg; k++) {
                    int t = g_tgt[st + k];
                    float e = s1v + g_t2[b * NN + t];
                    e = fmaxf(e, 0.2f * e);
                    float mn = fmaxf(m, e);
                    float sc = __expf(m - mn);
                    float wt = __expf(e - mn);
                    den = fmaf(den, sc, wt);
                    acc = fmaf(acc, sc, wt * g_h2[(size_t)(b * NN + t) * FOUT + j]);
                    m = mn;
                }
                outv = acc / den + bias;
            }
            out[(size_t)r * FOUT + j] = outv;
        }
    }
    gridbar(3);

    // ================= Phase 5: log_softmax (blocks 0..127) || state cleanup
    if (bid < 128) {
        int b = bid >> 6, o = bid & 63;
        const float* base = out + (size_t)b * NN * FOUT + o;
        float v0 = base[(size_t)tid * FOUT];
        float v1 = base[(size_t)(tid + NT) * FOUT];
        sred[tid] = fmaxf(v0, v1);
        __syncthreads();
        for (int st = 512; st > 0; st >>= 1) {
            if (tid < st) sred[tid] = fmaxf(sred[tid], sred[tid + st]);
            __syncthreads();
        }
        float mm = sred[0];
        __syncthreads();
        sred[tid] = __expf(v0 - mm) + __expf(v1 - mm);
        __syncthreads();
        for (int st = 512; st > 0; st >>= 1) {
            if (tid < st) sred[tid] += sred[tid + st];
            __syncthreads();
        }
        float lse = mm + __logf(sred[0]);
        float* basew = out + (size_t)b * NN * FOUT + o;
        basew[(size_t)tid * FOUT]        = v0 - lse;
        basew[(size_t)(tid + NT) * FOUT] = v1 - lse;
    } else {
        // restore launch-entry invariants: bitmap bits + means back to zero
        int cb = bid - 128;   // 0..19
        for (int i = cb * NT + tid; i < EE; i += 20 * NT) {
            int s = edges[i], t = edges[EE + i];
            unsigned bit = (unsigned)s * NN + (unsigned)t;
            atomicAnd(&g_bm[bit >> 5], ~(1u << (bit & 31u)));
        }
        if (cb == 0) {
            if (tid < BB * F1)                       g_mean1[tid] = 0.f;
            else if (tid < BB * F1 + BB * FOUT)      g_mean2[tid - BB * F1] = 0.f;
        }
    }
}

// ---------------- launch -------------------------------------------------------
extern "C" void kernel_launch(void* const* d_in, const int* in_sizes, int n_in,
                              void* d_out, int out_size) {
    const float* x     = (const float*)d_in[0];
    const int*   edges = (const int*)  d_in[1];
    const float* Wh    = (const float*)d_in[2];
    const float* ah    = (const float*)d_in[3];
    const float* bh    = (const float*)d_in[4];
    const float* Wo    = (const float*)d_in[5];
    const float* ao    = (const float*)d_in[6];
    const float* bo    = (const float*)d_in[7];
    float* out = (float*)d_out;

    mega<<<NB, NT>>>(x, edges, Wh, ah, bh, Wo, ao, bo, out);
}